// round 9
// baseline (speedup 1.0000x reference)
#include <cuda_runtime.h>
#include <cstdint>
#include <cstddef>

#define NN 50000
#define DD 256
#define EE 1000000
#define NB 196   // ceil(NN/256)

typedef unsigned long long u64;

// ---- device scratch (no malloc allowed) ----
__device__ float g_Y[2][NN][64];    // [m: 0=h,1=t][node][src-proj 64]
__device__ float g_a[2][NN][4];     // [m][node][ a_s h0, a_s h1, a_d h0, a_d h1 ]
__device__ float g_wv[4][DD];       // folded att vectors: [kind*2+h][k]
__device__ int   g_cnt[2][NN];      // in-degree histogram per direction
__device__ int   g_off[2][NN + 1];  // CSR offsets
__device__ int   g_cur[2][NN];      // scatter cursors
__device__ int   g_srcs[2][EE];     // edge sources sorted by dst
__device__ int   g_part[2][NB];     // per-block partials for scan
__device__ int   g_is64;            // edge_index dtype flag

__device__ __forceinline__ float elu1(float x) {
    return x > 0.f ? x : expm1f(x);
}

__device__ __forceinline__ u64 pack2(float lo, float hi) {
    u64 r; asm("mov.b64 %0, {%1,%2};" : "=l"(r) : "f"(lo), "f"(hi)); return r;
}
__device__ __forceinline__ void unpack2(u64 v, float& lo, float& hi) {
    asm("mov.b64 {%0,%1}, %2;" : "=f"(lo), "=f"(hi) : "l"(v));
}
__device__ __forceinline__ u64 ffma2(u64 a, u64 b, u64 c) {
    u64 d; asm("fma.rn.f32x2 %0, %1, %2, %3;" : "=l"(d) : "l"(a), "l"(b), "l"(c));
    return d;
}

// Detect int64 edge_index (odd 32-bit words all zero since values < 50000)
__global__ void detect_kernel(const int* __restrict__ ei32) {
    if (threadIdx.x == 0 && blockIdx.x == 0) {
        int z = ei32[1] | ei32[3] | ei32[5] | ei32[7] | ei32[9] | ei32[11] | ei32[13];
        g_is64 = (z == 0) ? 1 : 0;
        g_off[0][NN] = EE;
        g_off[1][NN] = EE;
    }
}

// fold attention vectors into W: g_wv[kind*2+h][k] = sum_c W[k][h*32+c]*att[h][c]
__global__ __launch_bounds__(256) void prep_wv_kernel(
    const float* __restrict__ Wsrc, const float* __restrict__ Wdst,
    const float* __restrict__ att_src, const float* __restrict__ att_dst)
{
    int idx = blockIdx.x * 256 + threadIdx.x;   // 0..1023
    if (idx >= 4 * DD) return;
    int q = idx >> 8;          // kind*2+h
    int k = idx & 255;
    int kind = q >> 1, h = q & 1;
    const float* W = kind ? Wdst : Wsrc;
    const float* att = kind ? att_dst : att_src;
    float s = 0.f;
    #pragma unroll
    for (int c = 0; c < 32; c++)
        s = fmaf(W[k * 64 + h * 32 + c], att[h * 32 + c], s);
    g_wv[q][k] = s;
}

// a[m][n][q] = elu(x_m[n]) . g_wv[q]  (warp per node)
__global__ __launch_bounds__(256) void gemv_a_kernel(
    const float* __restrict__ hx, const float* __restrict__ txp)
{
    int m = blockIdx.y;
    const float* __restrict__ X = (m == 0) ? hx : txp;
    int n = blockIdx.x * 8 + (threadIdx.x >> 5);
    if (n >= NN) return;
    int lane = threadIdx.x & 31;
    float s[4] = {0.f, 0.f, 0.f, 0.f};
    #pragma unroll
    for (int ch = 0; ch < 2; ch++) {
        int k = lane * 4 + ch * 128;
        float4 xv = *(const float4*)&X[(size_t)n * DD + k];
        xv.x = elu1(xv.x); xv.y = elu1(xv.y); xv.z = elu1(xv.z); xv.w = elu1(xv.w);
        #pragma unroll
        for (int q = 0; q < 4; q++) {
            float4 wv = *(const float4*)&g_wv[q][k];
            s[q] = fmaf(xv.x, wv.x, s[q]);
            s[q] = fmaf(xv.y, wv.y, s[q]);
            s[q] = fmaf(xv.z, wv.z, s[q]);
            s[q] = fmaf(xv.w, wv.w, s[q]);
        }
    }
    #pragma unroll
    for (int o = 16; o >= 1; o >>= 1) {
        #pragma unroll
        for (int q = 0; q < 4; q++)
            s[q] += __shfl_xor_sync(0xffffffffu, s[q], o);
    }
    if (lane == 0)
        *(float4*)&g_a[m][n][0] = make_float4(s[0], s[1], s[2], s[3]);
}

__global__ void zero_kernel() {
    int i = blockIdx.x * blockDim.x + threadIdx.x;
    if (i < 2 * NN) ((int*)g_cnt)[i] = 0;
}

__device__ __forceinline__ void load_edge(const void* eiv, int e, int& a, int& b) {
    if (g_is64) {
        const long long* ei = (const long long*)eiv;
        a = (int)__ldg(&ei[e]); b = (int)__ldg(&ei[EE + e]);
    } else {
        const int* ei = (const int*)eiv;
        a = __ldg(&ei[e]); b = __ldg(&ei[EE + e]);
    }
}

__global__ __launch_bounds__(256) void hist_kernel(const void* __restrict__ eiv) {
    int e = blockIdx.x * blockDim.x + threadIdx.x;
    if (e >= EE) return;
    int a, b;
    load_edge(eiv, e, a, b);
    atomicAdd(&g_cnt[0][b], 1);   // dir0: h->t, dst = b
    atomicAdd(&g_cnt[1][a], 1);   // dir1: t->h, dst = a
}

// exclusive block scan helper (256 threads)
__device__ __forceinline__ int block_exscan(int v, int* tot) {
    int lane = threadIdx.x & 31, wid = threadIdx.x >> 5;
    int inc = v;
    #pragma unroll
    for (int o = 1; o < 32; o <<= 1) {
        int n = __shfl_up_sync(0xffffffffu, inc, o);
        if (lane >= o) inc += n;
    }
    __shared__ int ws[8];
    if (lane == 31) ws[wid] = inc;
    __syncthreads();
    if (wid == 0) {
        int w = (lane < 8) ? ws[lane] : 0;
        #pragma unroll
        for (int o = 1; o < 8; o <<= 1) {
            int n = __shfl_up_sync(0xffffffffu, w, o);
            if (lane >= o) w += n;
        }
        if (lane < 8) ws[lane] = w;
    }
    __syncthreads();
    int base = (wid > 0) ? ws[wid - 1] : 0;
    *tot = ws[7];
    return base + inc - v;
}

__global__ __launch_bounds__(256) void scan1_kernel() {
    int dir = blockIdx.y;
    int idx = blockIdx.x * 256 + threadIdx.x;
    int c = (idx < NN) ? g_cnt[dir][idx] : 0;
    int tot;
    block_exscan(c, &tot);
    if (threadIdx.x == 0) g_part[dir][blockIdx.x] = tot;
}

__global__ __launch_bounds__(256) void scan2_kernel() {
    int dir = blockIdx.x;
    int v = (threadIdx.x < NB) ? g_part[dir][threadIdx.x] : 0;
    int tot;
    int ex = block_exscan(v, &tot);
    if (threadIdx.x < NB) g_part[dir][threadIdx.x] = ex;
}

__global__ __launch_bounds__(256) void scan3_kernel() {
    int dir = blockIdx.y;
    int idx = blockIdx.x * 256 + threadIdx.x;
    int c = (idx < NN) ? g_cnt[dir][idx] : 0;
    int tot;
    int ex = block_exscan(c, &tot) + g_part[dir][blockIdx.x];
    if (idx < NN) {
        g_off[dir][idx] = ex;
        g_cur[dir][idx] = ex;
    }
}

__global__ __launch_bounds__(256) void scatter_kernel(const void* __restrict__ eiv) {
    int e = blockIdx.x * blockDim.x + threadIdx.x;
    if (e >= EE) return;
    int a, b;
    load_edge(eiv, e, a, b);
    int p0 = atomicAdd(&g_cur[0][b], 1);
    g_srcs[0][p0] = a;
    int p1 = atomicAdd(&g_cur[1][a], 1);
    g_srcs[1][p1] = b;
}

// Y[m] = elu(X_m) @ W_src, M=50000, N=64, K=256.
// Block tile 64x64, thread tile 8 rows x 2 cols (f32x2 row-pairs),
// A-loads warp-broadcast.
__global__ __launch_bounds__(256, 4) void gemm_kernel(
    const float* __restrict__ hx, const float* __restrict__ txp,
    const float* __restrict__ Wsrc)
{
    const int m = blockIdx.y;
    const float* __restrict__ X = (m == 0) ? hx : txp;
    __shared__ __align__(16) float As[32][68];    // [k][row]; 272B row stride
    __shared__ float2 Bs[32][32];                 // [k][col-pair]
    const int tid = threadIdx.x;
    const int tcx = tid & 31, tcy = tid >> 5;     // tcx: col pair (2 cols), tcy: warp (8 rows)
    const int row0 = blockIdx.x * 64;

    // acc2[rp][j]: rows (tcy*8 + 2rp, +1), col tcx*2 + j
    u64 acc2[4][2];
    #pragma unroll
    for (int rp = 0; rp < 4; rp++) {
        acc2[rp][0] = 0ull; acc2[rp][1] = 0ull;
    }

    for (int k0 = 0; k0 < DD; k0 += 32) {
        // A tile: 64 rows x 32 k (512 float4, 2 per thread)
        #pragma unroll
        for (int it = 0; it < 2; it++) {
            int l = tid + 256 * it;
            int r = l >> 3, k4 = l & 7;
            int grow = row0 + r;
            float4 v = make_float4(0.f, 0.f, 0.f, 0.f);
            if (grow < NN) v = *(const float4*)&X[(size_t)grow * DD + k0 + k4 * 4];
            As[k4*4+0][r] = elu1(v.x);
            As[k4*4+1][r] = elu1(v.y);
            As[k4*4+2][r] = elu1(v.z);
            As[k4*4+3][r] = elu1(v.w);
        }
        // B tile: 32 k x 64 cols (512 float4, 2 per thread)
        #pragma unroll
        for (int it = 0; it < 2; it++) {
            int l = tid + 256 * it;
            int kk = l >> 4, j4 = l & 15;
            float4 v = *(const float4*)&Wsrc[(size_t)(k0 + kk) * 64 + j4 * 4];
            Bs[kk][j4 * 2]     = make_float2(v.x, v.y);
            Bs[kk][j4 * 2 + 1] = make_float2(v.z, v.w);
        }
        __syncthreads();
        #pragma unroll
        for (int kk = 0; kk < 32; kk++) {
            u64 a2[4];
            #pragma unroll
            for (int q = 0; q < 2; q++) {
                ulonglong2 t = *(const ulonglong2*)&As[kk][tcy * 8 + q * 4];
                a2[q*2]   = t.x;
                a2[q*2+1] = t.y;
            }
            float2 bv = Bs[kk][tcx];
            u64 bb0 = pack2(bv.x, bv.x);
            u64 bb1 = pack2(bv.y, bv.y);
            #pragma unroll
            for (int rp = 0; rp < 4; rp++) {
                acc2[rp][0] = ffma2(a2[rp], bb0, acc2[rp][0]);
                acc2[rp][1] = ffma2(a2[rp], bb1, acc2[rp][1]);
            }
        }
        __syncthreads();
    }

    #pragma unroll
    for (int rp = 0; rp < 4; rp++) {
        float lo0, hi0, lo1, hi1;
        unpack2(acc2[rp][0], lo0, hi0);
        unpack2(acc2[rp][1], lo1, hi1);
        int grow = row0 + tcy * 8 + rp * 2;
        if (grow < NN)
            *(float2*)&g_Y[m][grow][tcx * 2] = make_float2(lo0, lo1);
        if (grow + 1 < NN)
            *(float2*)&g_Y[m][grow + 1][tcx * 2] = make_float2(hi0, hi1);
    }
}

// One warp per (node, dir): gather CSR segment, fused softmax + weighted sum.
__global__ __launch_bounds__(256) void aggr_kernel(float* __restrict__ out,
                                                   const float* __restrict__ bias) {
    int warp = (blockIdx.x * 256 + threadIdx.x) >> 5;
    if (warp >= 2 * NN) return;
    int lane = threadIdx.x & 31;
    int dir = warp >= NN;
    int i = warp - dir * NN;
    int half = lane >> 4;
    int c4 = lane & 15;
    int h = (lane >> 3) & 1;
    int ms = dir, md = 1 - dir;

    float a_d = g_a[md][i][2 + h];
    float den = 0.f;
    float4 num = make_float4(0.f, 0.f, 0.f, 0.f);

    if (half == 0) {  // self loop
        float al = g_a[ms][i][h] + a_d;
        al = al > 0.f ? al : 0.2f * al;
        float ea = __expf(al);
        den = ea;
        float4 v = *(const float4*)&g_Y[ms][i][c4 * 4];
        num.x = ea * v.x; num.y = ea * v.y; num.z = ea * v.z; num.w = ea * v.w;
    }

    int beg = g_off[dir][i], end = g_off[dir][i + 1];
    for (int j = beg + half; j < end; j += 2) {
        int s = g_srcs[dir][j];
        float al = g_a[ms][s][h] + a_d;
        al = al > 0.f ? al : 0.2f * al;
        float ea = __expf(al);
        den += ea;
        float4 v = *(const float4*)&g_Y[ms][s][c4 * 4];
        num.x = fmaf(ea, v.x, num.x);
        num.y = fmaf(ea, v.y, num.y);
        num.z = fmaf(ea, v.z, num.z);
        num.w = fmaf(ea, v.w, num.w);
    }

    num.x += __shfl_xor_sync(0xffffffffu, num.x, 16);
    num.y += __shfl_xor_sync(0xffffffffu, num.y, 16);
    num.z += __shfl_xor_sync(0xffffffffu, num.z, 16);
    num.w += __shfl_xor_sync(0xffffffffu, num.w, 16);
    den   += __shfl_xor_sync(0xffffffffu, den,   16);

    if (half == 0) {
        float w = 1.f / (den + 1e-16f);
        float4 b = ((const float4*)bias)[c4];
        float4 o = make_float4(fmaf(num.x, w, b.x), fmaf(num.y, w, b.y),
                               fmaf(num.z, w, b.z), fmaf(num.w, w, b.w));
        float* dp = out + ((dir == 0) ? (size_t)NN * 64 : (size_t)0)
                        + (size_t)i * 64 + c4 * 4;
        *(float4*)dp = o;
    }
}

extern "C" void kernel_launch(void* const* d_in, const int* in_sizes, int n_in,
                              void* d_out, int out_size) {
    const float* hx      = (const float*)d_in[0];
    const float* txp     = (const float*)d_in[1];
    const void*  ei      = d_in[2];               // int32 or int64, auto-detected
    const float* Wsrc    = (const float*)d_in[3];
    const float* Wdst    = (const float*)d_in[4];
    const float* att_src = (const float*)d_in[5];
    const float* att_dst = (const float*)d_in[6];
    const float* bias    = (const float*)d_in[7];
    float* out = (float*)d_out;

    detect_kernel<<<1, 32>>>((const int*)ei);
    prep_wv_kernel<<<4, 256>>>(Wsrc, Wdst, att_src, att_dst);
    zero_kernel<<<(2 * NN + 255) / 256, 256>>>();
    gemm_kernel<<<dim3((NN + 63) / 64, 2), 256>>>(hx, txp, Wsrc);
    gemv_a_kernel<<<dim3((NN + 7) / 8, 2), 256>>>(hx, txp);
    hist_kernel<<<(EE + 255) / 256, 256>>>(ei);
    scan1_kernel<<<dim3(NB, 2), 256>>>();
    scan2_kernel<<<2, 256>>>();
    scan3_kernel<<<dim3(NB, 2), 256>>>();
    scatter_kernel<<<(EE + 255) / 256, 256>>>(ei);
    aggr_kernel<<<(2 * NN * 32 + 255) / 256, 256>>>(out, bias);
}

// round 10
// speedup vs baseline: 1.1329x; 1.1329x over previous
#include <cuda_runtime.h>
#include <cstdint>
#include <cstddef>

#define NN 50000
#define DD 256
#define EE 1000000
#define NB 196   // ceil(NN/256)

typedef unsigned long long u64;

// ---- device scratch (no malloc allowed) ----
__device__ float g_Y[2][NN][64];    // [m: 0=h,1=t][node][src-proj 64]
__device__ float g_a[2][NN][4];     // [m][node][ a_s h0, a_s h1, a_d h0, a_d h1 ]
__device__ float g_wv[4][DD];       // folded att vectors: [kind*2+h][k]
__device__ int   g_cnt[2][NN];      // in-degree histogram per direction
__device__ int   g_off[2][NN + 1];  // CSR offsets
__device__ int   g_cur[2][NN];      // scatter cursors
__device__ int   g_srcs[2][EE];     // edge sources sorted by dst
__device__ int   g_part[2][NB];     // per-block partials for scan
__device__ int   g_is64;            // edge_index dtype flag

__device__ __forceinline__ float elu1(float x) {
    return x > 0.f ? x : expm1f(x);
}

__device__ __forceinline__ u64 pack2(float lo, float hi) {
    u64 r; asm("mov.b64 %0, {%1,%2};" : "=l"(r) : "f"(lo), "f"(hi)); return r;
}
__device__ __forceinline__ void unpack2(u64 v, float& lo, float& hi) {
    asm("mov.b64 {%0,%1}, %2;" : "=f"(lo), "=f"(hi) : "l"(v));
}
__device__ __forceinline__ u64 ffma2(u64 a, u64 b, u64 c) {
    u64 d; asm("fma.rn.f32x2 %0, %1, %2, %3;" : "=l"(d) : "l"(a), "l"(b), "l"(c));
    return d;
}

// Detect int64 edge_index (odd 32-bit words all zero since values < 50000)
__global__ void detect_kernel(const int* __restrict__ ei32) {
    if (threadIdx.x == 0 && blockIdx.x == 0) {
        int z = ei32[1] | ei32[3] | ei32[5] | ei32[7] | ei32[9] | ei32[11] | ei32[13];
        g_is64 = (z == 0) ? 1 : 0;
        g_off[0][NN] = EE;
        g_off[1][NN] = EE;
    }
}

// fold attention vectors into W: g_wv[kind*2+h][k] = sum_c W[k][h*32+c]*att[h][c]
__global__ __launch_bounds__(256) void prep_wv_kernel(
    const float* __restrict__ Wsrc, const float* __restrict__ Wdst,
    const float* __restrict__ att_src, const float* __restrict__ att_dst)
{
    int idx = blockIdx.x * 256 + threadIdx.x;   // 0..1023
    if (idx >= 4 * DD) return;
    int q = idx >> 8;          // kind*2+h
    int k = idx & 255;
    int kind = q >> 1, h = q & 1;
    const float* W = kind ? Wdst : Wsrc;
    const float* att = kind ? att_dst : att_src;
    float s = 0.f;
    #pragma unroll
    for (int c = 0; c < 32; c++)
        s = fmaf(W[k * 64 + h * 32 + c], att[h * 32 + c], s);
    g_wv[q][k] = s;
}

__global__ void zero_kernel() {
    int i = blockIdx.x * blockDim.x + threadIdx.x;
    if (i < 2 * NN) ((int*)g_cnt)[i] = 0;
}

__device__ __forceinline__ void load_edge(const void* eiv, int e, int& a, int& b) {
    if (g_is64) {
        const long long* ei = (const long long*)eiv;
        a = (int)__ldg(&ei[e]); b = (int)__ldg(&ei[EE + e]);
    } else {
        const int* ei = (const int*)eiv;
        a = __ldg(&ei[e]); b = __ldg(&ei[EE + e]);
    }
}

__global__ __launch_bounds__(256) void hist_kernel(const void* __restrict__ eiv) {
    int e = blockIdx.x * blockDim.x + threadIdx.x;
    if (e >= EE) return;
    int a, b;
    load_edge(eiv, e, a, b);
    atomicAdd(&g_cnt[0][b], 1);   // dir0: h->t, dst = b
    atomicAdd(&g_cnt[1][a], 1);   // dir1: t->h, dst = a
}

// exclusive block scan helper (256 threads)
__device__ __forceinline__ int block_exscan(int v, int* tot) {
    int lane = threadIdx.x & 31, wid = threadIdx.x >> 5;
    int inc = v;
    #pragma unroll
    for (int o = 1; o < 32; o <<= 1) {
        int n = __shfl_up_sync(0xffffffffu, inc, o);
        if (lane >= o) inc += n;
    }
    __shared__ int ws[8];
    if (lane == 31) ws[wid] = inc;
    __syncthreads();
    if (wid == 0) {
        int w = (lane < 8) ? ws[lane] : 0;
        #pragma unroll
        for (int o = 1; o < 8; o <<= 1) {
            int n = __shfl_up_sync(0xffffffffu, w, o);
            if (lane >= o) w += n;
        }
        if (lane < 8) ws[lane] = w;
    }
    __syncthreads();
    int base = (wid > 0) ? ws[wid - 1] : 0;
    *tot = ws[7];
    return base + inc - v;
}

__global__ __launch_bounds__(256) void scan1_kernel() {
    int dir = blockIdx.y;
    int idx = blockIdx.x * 256 + threadIdx.x;
    int c = (idx < NN) ? g_cnt[dir][idx] : 0;
    int tot;
    block_exscan(c, &tot);
    if (threadIdx.x == 0) g_part[dir][blockIdx.x] = tot;
}

__global__ __launch_bounds__(256) void scan2_kernel() {
    int dir = blockIdx.x;
    int v = (threadIdx.x < NB) ? g_part[dir][threadIdx.x] : 0;
    int tot;
    int ex = block_exscan(v, &tot);
    if (threadIdx.x < NB) g_part[dir][threadIdx.x] = ex;
}

__global__ __launch_bounds__(256) void scan3_kernel() {
    int dir = blockIdx.y;
    int idx = blockIdx.x * 256 + threadIdx.x;
    int c = (idx < NN) ? g_cnt[dir][idx] : 0;
    int tot;
    int ex = block_exscan(c, &tot) + g_part[dir][blockIdx.x];
    if (idx < NN) {
        g_off[dir][idx] = ex;
        g_cur[dir][idx] = ex;
    }
}

__global__ __launch_bounds__(256) void scatter_kernel(const void* __restrict__ eiv) {
    int e = blockIdx.x * blockDim.x + threadIdx.x;
    if (e >= EE) return;
    int a, b;
    load_edge(eiv, e, a, b);
    int p0 = atomicAdd(&g_cur[0][b], 1);
    g_srcs[0][p0] = a;
    int p1 = atomicAdd(&g_cur[1][a], 1);
    g_srcs[1][p1] = b;
}

// Y[m] = elu(X_m) @ W_src (M=50000, N=64, K=256), block tile 64x64,
// thread tile 8x2 (f32x2 row-pairs), A-loads warp-broadcast.
// Fused: per-node attention logits a[q] = elu(x) . g_wv[q] accumulated
// from the As tile (one (row,q) pair per thread) — no extra DRAM traffic.
__global__ __launch_bounds__(256, 4) void gemm_kernel(
    const float* __restrict__ hx, const float* __restrict__ txp,
    const float* __restrict__ Wsrc)
{
    const int m = blockIdx.y;
    const float* __restrict__ X = (m == 0) ? hx : txp;
    __shared__ __align__(16) float As[32][68];    // [k][row]; 272B row stride
    __shared__ float2 Bs[32][32];                 // [k][col-pair]
    __shared__ float  Ws[32][4];                  // wv chunk [kk][q]
    const int tid = threadIdx.x;
    const int tcx = tid & 31, tcy = tid >> 5;     // tcx: col pair, tcy: warp (8 rows)
    const int row0 = blockIdx.x * 64;
    const int arow = tid & 63, aq = tid >> 6;     // this thread's logit assignment

    u64 acc2[4][2];
    #pragma unroll
    for (int rp = 0; rp < 4; rp++) {
        acc2[rp][0] = 0ull; acc2[rp][1] = 0ull;
    }
    float sa = 0.f;

    for (int k0 = 0; k0 < DD; k0 += 32) {
        // A tile: 64 rows x 32 k (512 float4, 2 per thread)
        #pragma unroll
        for (int it = 0; it < 2; it++) {
            int l = tid + 256 * it;
            int r = l >> 3, k4 = l & 7;
            int grow = row0 + r;
            float4 v = make_float4(0.f, 0.f, 0.f, 0.f);
            if (grow < NN) v = *(const float4*)&X[(size_t)grow * DD + k0 + k4 * 4];
            As[k4*4+0][r] = elu1(v.x);
            As[k4*4+1][r] = elu1(v.y);
            As[k4*4+2][r] = elu1(v.z);
            As[k4*4+3][r] = elu1(v.w);
        }
        // B tile: 32 k x 64 cols
        #pragma unroll
        for (int it = 0; it < 2; it++) {
            int l = tid + 256 * it;
            int kk = l >> 4, j4 = l & 15;
            float4 v = *(const float4*)&Wsrc[(size_t)(k0 + kk) * 64 + j4 * 4];
            Bs[kk][j4 * 2]     = make_float2(v.x, v.y);
            Bs[kk][j4 * 2 + 1] = make_float2(v.z, v.w);
        }
        // wv chunk: 32 k x 4 q
        if (tid < 128) Ws[tid >> 2][tid & 3] = g_wv[tid & 3][k0 + (tid >> 2)];
        __syncthreads();
        #pragma unroll
        for (int kk = 0; kk < 32; kk++) {
            u64 a2[4];
            #pragma unroll
            for (int q = 0; q < 2; q++) {
                ulonglong2 t = *(const ulonglong2*)&As[kk][tcy * 8 + q * 4];
                a2[q*2]   = t.x;
                a2[q*2+1] = t.y;
            }
            float2 bv = Bs[kk][tcx];
            u64 bb0 = pack2(bv.x, bv.x);
            u64 bb1 = pack2(bv.y, bv.y);
            #pragma unroll
            for (int rp = 0; rp < 4; rp++) {
                acc2[rp][0] = ffma2(a2[rp], bb0, acc2[rp][0]);
                acc2[rp][1] = ffma2(a2[rp], bb1, acc2[rp][1]);
            }
        }
        // logit partial for this thread's (row, q)
        #pragma unroll
        for (int kk = 0; kk < 32; kk++)
            sa = fmaf(As[kk][arow], Ws[kk][aq], sa);
        __syncthreads();
    }

    #pragma unroll
    for (int rp = 0; rp < 4; rp++) {
        float lo0, hi0, lo1, hi1;
        unpack2(acc2[rp][0], lo0, hi0);
        unpack2(acc2[rp][1], lo1, hi1);
        int grow = row0 + tcy * 8 + rp * 2;
        if (grow < NN)
            *(float2*)&g_Y[m][grow][tcx * 2] = make_float2(lo0, lo1);
        if (grow + 1 < NN)
            *(float2*)&g_Y[m][grow + 1][tcx * 2] = make_float2(hi0, hi1);
    }
    if (row0 + arow < NN) g_a[m][row0 + arow][aq] = sa;
}

// One warp per (node, dir): gather CSR segment, fused softmax + weighted sum.
__global__ __launch_bounds__(256) void aggr_kernel(float* __restrict__ out,
                                                   const float* __restrict__ bias) {
    int warp = (blockIdx.x * 256 + threadIdx.x) >> 5;
    if (warp >= 2 * NN) return;
    int lane = threadIdx.x & 31;
    int dir = warp >= NN;
    int i = warp - dir * NN;
    int half = lane >> 4;
    int c4 = lane & 15;
    int h = (lane >> 3) & 1;
    int ms = dir, md = 1 - dir;

    float a_d = g_a[md][i][2 + h];
    float den = 0.f;
    float4 num = make_float4(0.f, 0.f, 0.f, 0.f);

    if (half == 0) {  // self loop
        float al = g_a[ms][i][h] + a_d;
        al = al > 0.f ? al : 0.2f * al;
        float ea = __expf(al);
        den = ea;
        float4 v = *(const float4*)&g_Y[ms][i][c4 * 4];
        num.x = ea * v.x; num.y = ea * v.y; num.z = ea * v.z; num.w = ea * v.w;
    }

    int beg = g_off[dir][i], end = g_off[dir][i + 1];
    for (int j = beg + half; j < end; j += 2) {
        int s = g_srcs[dir][j];
        float al = g_a[ms][s][h] + a_d;
        al = al > 0.f ? al : 0.2f * al;
        float ea = __expf(al);
        den += ea;
        float4 v = *(const float4*)&g_Y[ms][s][c4 * 4];
        num.x = fmaf(ea, v.x, num.x);
        num.y = fmaf(ea, v.y, num.y);
        num.z = fmaf(ea, v.z, num.z);
        num.w = fmaf(ea, v.w, num.w);
    }

    num.x += __shfl_xor_sync(0xffffffffu, num.x, 16);
    num.y += __shfl_xor_sync(0xffffffffu, num.y, 16);
    num.z += __shfl_xor_sync(0xffffffffu, num.z, 16);
    num.w += __shfl_xor_sync(0xffffffffu, num.w, 16);
    den   += __shfl_xor_sync(0xffffffffu, den,   16);

    if (half == 0) {
        float w = 1.f / (den + 1e-16f);
        float4 b = ((const float4*)bias)[c4];
        float4 o = make_float4(fmaf(num.x, w, b.x), fmaf(num.y, w, b.y),
                               fmaf(num.z, w, b.z), fmaf(num.w, w, b.w));
        float* dp = out + ((dir == 0) ? (size_t)NN * 64 : (size_t)0)
                        + (size_t)i * 64 + c4 * 4;
        *(float4*)dp = o;
    }
}

extern "C" void kernel_launch(void* const* d_in, const int* in_sizes, int n_in,
                              void* d_out, int out_size) {
    const float* hx      = (const float*)d_in[0];
    const float* txp     = (const float*)d_in[1];
    const void*  ei      = d_in[2];               // int32 or int64, auto-detected
    const float* Wsrc    = (const float*)d_in[3];
    const float* Wdst    = (const float*)d_in[4];
    const float* att_src = (const float*)d_in[5];
    const float* att_dst = (const float*)d_in[6];
    const float* bias    = (const float*)d_in[7];
    float* out = (float*)d_out;

    detect_kernel<<<1, 32>>>((const int*)ei);
    prep_wv_kernel<<<4, 256>>>(Wsrc, Wdst, att_src, att_dst);
    zero_kernel<<<(2 * NN + 255) / 256, 256>>>();
    gemm_kernel<<<dim3((NN + 63) / 64, 2), 256>>>(hx, txp, Wsrc);
    hist_kernel<<<(EE + 255) / 256, 256>>>(ei);
    scan1_kernel<<<dim3(NB, 2), 256>>>();
    scan2_kernel<<<2, 256>>>();
    scan3_kernel<<<dim3(NB, 2), 256>>>();
    scatter_kernel<<<(EE + 255) / 256, 256>>>(ei);
    aggr_kernel<<<(2 * NN * 32 + 255) / 256, 256>>>(out, bias);
}

// round 11
// speedup vs baseline: 1.2181x; 1.0752x over previous
#include <cuda_runtime.h>
#include <cstdint>
#include <cstddef>

#define NN 50000
#define DD 256
#define EE 1000000
#define NB 196   // ceil(NN/256)

typedef unsigned long long u64;

// ---- device scratch (no malloc allowed) ----
__device__ float g_Y[2][NN][64];    // [m: 0=h,1=t][node][src-proj 64]
__device__ float g_a[2][NN][4];     // [m][node][ a_s h0, a_s h1, a_d h0, a_d h1 ]
__device__ float g_wv[4][DD];       // folded att vectors: [kind*2+h][k]
__device__ int   g_cnt[2][NN];      // in-degree histogram per direction
__device__ int   g_off[2][NN + 1];  // CSR offsets
__device__ int   g_cur[2][NN];      // scatter cursors
__device__ int   g_srcs[2][EE];     // edge sources sorted by dst
__device__ int   g_part[2][NB];     // per-block partials for scan
__device__ int   g_is64;            // edge_index dtype flag

__device__ __forceinline__ float elu1(float x) {
    return x > 0.f ? x : expm1f(x);
}

__device__ __forceinline__ u64 pack2(float lo, float hi) {
    u64 r; asm("mov.b64 %0, {%1,%2};" : "=l"(r) : "f"(lo), "f"(hi)); return r;
}
__device__ __forceinline__ void unpack2(u64 v, float& lo, float& hi) {
    asm("mov.b64 {%0,%1}, %2;" : "=f"(lo), "=f"(hi) : "l"(v));
}
__device__ __forceinline__ u64 ffma2(u64 a, u64 b, u64 c) {
    u64 d; asm("fma.rn.f32x2 %0, %1, %2, %3;" : "=l"(d) : "l"(a), "l"(b), "l"(c));
    return d;
}

// Detect int64 edge_index (odd 32-bit words all zero since values < 50000)
__global__ void detect_kernel(const int* __restrict__ ei32) {
    if (threadIdx.x == 0 && blockIdx.x == 0) {
        int z = ei32[1] | ei32[3] | ei32[5] | ei32[7] | ei32[9] | ei32[11] | ei32[13];
        g_is64 = (z == 0) ? 1 : 0;
        g_off[0][NN] = EE;
        g_off[1][NN] = EE;
    }
}

// fold attention vectors into W: g_wv[kind*2+h][k] = sum_c W[k][h*32+c]*att[h][c]
__global__ __launch_bounds__(256) void prep_wv_kernel(
    const float* __restrict__ Wsrc, const float* __restrict__ Wdst,
    const float* __restrict__ att_src, const float* __restrict__ att_dst)
{
    int idx = blockIdx.x * 256 + threadIdx.x;   // 0..1023
    if (idx >= 4 * DD) return;
    int q = idx >> 8;          // kind*2+h
    int k = idx & 255;
    int kind = q >> 1, h = q & 1;
    const float* W = kind ? Wdst : Wsrc;
    const float* att = kind ? att_dst : att_src;
    float s = 0.f;
    #pragma unroll
    for (int c = 0; c < 32; c++)
        s = fmaf(W[k * 64 + h * 32 + c], att[h * 32 + c], s);
    g_wv[q][k] = s;
}

__global__ void zero_kernel() {
    int i = blockIdx.x * blockDim.x + threadIdx.x;
    if (i < 2 * NN) ((int*)g_cnt)[i] = 0;
}

__device__ __forceinline__ void load_edge(const void* eiv, int e, int& a, int& b) {
    if (g_is64) {
        const long long* ei = (const long long*)eiv;
        a = (int)__ldg(&ei[e]); b = (int)__ldg(&ei[EE + e]);
    } else {
        const int* ei = (const int*)eiv;
        a = __ldg(&ei[e]); b = __ldg(&ei[EE + e]);
    }
}

__global__ __launch_bounds__(256) void hist_kernel(const void* __restrict__ eiv) {
    int e = blockIdx.x * blockDim.x + threadIdx.x;
    if (e >= EE) return;
    int a, b;
    load_edge(eiv, e, a, b);
    atomicAdd(&g_cnt[0][b], 1);   // dir0: h->t, dst = b
    atomicAdd(&g_cnt[1][a], 1);   // dir1: t->h, dst = a
}

// exclusive block scan helper (256 threads)
__device__ __forceinline__ int block_exscan(int v, int* tot) {
    int lane = threadIdx.x & 31, wid = threadIdx.x >> 5;
    int inc = v;
    #pragma unroll
    for (int o = 1; o < 32; o <<= 1) {
        int n = __shfl_up_sync(0xffffffffu, inc, o);
        if (lane >= o) inc += n;
    }
    __shared__ int ws[8];
    if (lane == 31) ws[wid] = inc;
    __syncthreads();
    if (wid == 0) {
        int w = (lane < 8) ? ws[lane] : 0;
        #pragma unroll
        for (int o = 1; o < 8; o <<= 1) {
            int n = __shfl_up_sync(0xffffffffu, w, o);
            if (lane >= o) w += n;
        }
        if (lane < 8) ws[lane] = w;
    }
    __syncthreads();
    int base = (wid > 0) ? ws[wid - 1] : 0;
    *tot = ws[7];
    return base + inc - v;
}

__global__ __launch_bounds__(256) void scan1_kernel() {
    int dir = blockIdx.y;
    int idx = blockIdx.x * 256 + threadIdx.x;
    int c = (idx < NN) ? g_cnt[dir][idx] : 0;
    int tot;
    block_exscan(c, &tot);
    if (threadIdx.x == 0) g_part[dir][blockIdx.x] = tot;
}

__global__ __launch_bounds__(256) void scan2_kernel() {
    int dir = blockIdx.x;
    int v = (threadIdx.x < NB) ? g_part[dir][threadIdx.x] : 0;
    int tot;
    int ex = block_exscan(v, &tot);
    if (threadIdx.x < NB) g_part[dir][threadIdx.x] = ex;
}

__global__ __launch_bounds__(256) void scan3_kernel() {
    int dir = blockIdx.y;
    int idx = blockIdx.x * 256 + threadIdx.x;
    int c = (idx < NN) ? g_cnt[dir][idx] : 0;
    int tot;
    int ex = block_exscan(c, &tot) + g_part[dir][blockIdx.x];
    if (idx < NN) {
        g_off[dir][idx] = ex;
        g_cur[dir][idx] = ex;
    }
}

__global__ __launch_bounds__(256) void scatter_kernel(const void* __restrict__ eiv) {
    int e = blockIdx.x * blockDim.x + threadIdx.x;
    if (e >= EE) return;
    int a, b;
    load_edge(eiv, e, a, b);
    int p0 = atomicAdd(&g_cur[0][b], 1);
    g_srcs[0][p0] = a;
    int p1 = atomicAdd(&g_cur[1][a], 1);
    g_srcs[1][p1] = b;
}

// Y[m] = elu(X_m) @ W_src (M=50000, N=64, K=256).
// Block tile 128x64, thread tile 8 rows x 4 cols (f32x2 row-pairs).
// a_s (src logits) computed from accumulators in the epilogue (Y . att_src);
// a_d (dst logits) via f32x2 smem loop on threads 0..127.
__global__ __launch_bounds__(256, 3) void gemm_kernel(
    const float* __restrict__ hx, const float* __restrict__ txp,
    const float* __restrict__ Wsrc, const float* __restrict__ att_src)
{
    const int m = blockIdx.y;
    const float* __restrict__ X = (m == 0) ? hx : txp;
    __shared__ __align__(16) float As[32][132];   // [k][row], 528B stride
    __shared__ float4 Bs[32][16];                 // [k][col4] (64 cols)
    __shared__ float  Wch[2][32];                 // wv[2],wv[3] chunk
    const int tid = threadIdx.x;
    const int tcx = tid & 15, tcy = tid >> 4;     // col-group(4 cols), row-group(8 rows)
    const int row0 = blockIdx.x * 128;
    const int pair = tid & 63, aq = tid >> 6;     // logit assignment (tid<128): row-pair, q-2

    u64 acc2[4][4];       // [row-pair][col]
    #pragma unroll
    for (int rp = 0; rp < 4; rp++)
        #pragma unroll
        for (int j = 0; j < 4; j++) acc2[rp][j] = 0ull;
    u64 sa2 = 0ull;       // packed a_d partials for (row-pair, q)

    for (int k0 = 0; k0 < DD; k0 += 32) {
        // A tile: 128 rows x 32 k (1024 float4, 4 per thread)
        #pragma unroll
        for (int it = 0; it < 4; it++) {
            int l = tid + 256 * it;
            int r = l >> 3, k4 = l & 7;
            int grow = row0 + r;
            float4 v = make_float4(0.f, 0.f, 0.f, 0.f);
            if (grow < NN) v = *(const float4*)&X[(size_t)grow * DD + k0 + k4 * 4];
            As[k4*4+0][r] = elu1(v.x);
            As[k4*4+1][r] = elu1(v.y);
            As[k4*4+2][r] = elu1(v.z);
            As[k4*4+3][r] = elu1(v.w);
        }
        // B tile: 32 k x 64 cols (512 float4, 2 per thread)
        #pragma unroll
        for (int it = 0; it < 2; it++) {
            int l = tid + 256 * it;
            int kk = l >> 4, j4 = l & 15;
            Bs[kk][j4] = *(const float4*)&Wsrc[(size_t)(k0 + kk) * 64 + j4 * 4];
        }
        // wv chunk for q=2,3
        if (tid < 64) Wch[tid >> 5][tid & 31] = g_wv[2 + (tid >> 5)][k0 + (tid & 31)];
        __syncthreads();

        #pragma unroll
        for (int kk = 0; kk < 32; kk++) {
            u64 a2[4];
            #pragma unroll
            for (int q = 0; q < 2; q++) {
                ulonglong2 t = *(const ulonglong2*)&As[kk][tcy * 8 + q * 4];
                a2[q*2]   = t.x;
                a2[q*2+1] = t.y;
            }
            float4 bv = Bs[kk][tcx];
            u64 bb[4];
            bb[0] = pack2(bv.x, bv.x); bb[1] = pack2(bv.y, bv.y);
            bb[2] = pack2(bv.z, bv.z); bb[3] = pack2(bv.w, bv.w);
            #pragma unroll
            for (int rp = 0; rp < 4; rp++)
                #pragma unroll
                for (int j = 0; j < 4; j++)
                    acc2[rp][j] = ffma2(a2[rp], bb[j], acc2[rp][j]);
        }

        // a_d partials: threads 0..127, one (row-pair, q) each
        if (tid < 128) {
            const float* wrow = Wch[aq];
            #pragma unroll
            for (int k4 = 0; k4 < 8; k4++) {
                float4 w4 = *(const float4*)&wrow[k4 * 4];
                u64 p0 = *(const u64*)&As[k4*4+0][pair * 2];
                u64 p1 = *(const u64*)&As[k4*4+1][pair * 2];
                u64 p2 = *(const u64*)&As[k4*4+2][pair * 2];
                u64 p3 = *(const u64*)&As[k4*4+3][pair * 2];
                sa2 = ffma2(p0, pack2(w4.x, w4.x), sa2);
                sa2 = ffma2(p1, pack2(w4.y, w4.y), sa2);
                sa2 = ffma2(p2, pack2(w4.z, w4.z), sa2);
                sa2 = ffma2(p3, pack2(w4.w, w4.w), sa2);
            }
        }
        __syncthreads();
    }

    // epilogue: store Y; a_s from accumulators (h = tcx>>3)
    float attv[4];
    {
        int base = (tcx >> 3) * 32 + (tcx & 7) * 4;
        #pragma unroll
        for (int j = 0; j < 4; j++) attv[j] = att_src[base + j];
    }
    #pragma unroll
    for (int rp = 0; rp < 4; rp++) {
        float lo[4], hi[4];
        #pragma unroll
        for (int j = 0; j < 4; j++) unpack2(acc2[rp][j], lo[j], hi[j]);
        #pragma unroll
        for (int half = 0; half < 2; half++) {
            const float* accr = half ? hi : lo;
            int grow = row0 + tcy * 8 + rp * 2 + half;
            float part = 0.f;
            #pragma unroll
            for (int j = 0; j < 4; j++) part = fmaf(accr[j], attv[j], part);
            part += __shfl_xor_sync(0xffffffffu, part, 1);
            part += __shfl_xor_sync(0xffffffffu, part, 2);
            part += __shfl_xor_sync(0xffffffffu, part, 4);
            if (grow < NN) {
                *(float4*)&g_Y[m][grow][tcx * 4] =
                    make_float4(accr[0], accr[1], accr[2], accr[3]);
                if ((tcx & 7) == 0) g_a[m][grow][tcx >> 3] = part;
            }
        }
    }
    // a_d stores
    if (tid < 128) {
        float s0, s1;
        unpack2(sa2, s0, s1);
        int grow = row0 + pair * 2;
        if (grow < NN)     g_a[m][grow][2 + aq] = s0;
        if (grow + 1 < NN) g_a[m][grow + 1][2 + aq] = s1;
    }
}

// One warp per (node, dir): gather CSR segment, fused softmax + weighted sum.
__global__ __launch_bounds__(256) void aggr_kernel(float* __restrict__ out,
                                                   const float* __restrict__ bias) {
    int warp = (blockIdx.x * 256 + threadIdx.x) >> 5;
    if (warp >= 2 * NN) return;
    int lane = threadIdx.x & 31;
    int dir = warp >= NN;
    int i = warp - dir * NN;
    int half = lane >> 4;
    int c4 = lane & 15;
    int h = (lane >> 3) & 1;
    int ms = dir, md = 1 - dir;

    float a_d = g_a[md][i][2 + h];
    float den = 0.f;
    float4 num = make_float4(0.f, 0.f, 0.f, 0.f);

    if (half == 0) {  // self loop
        float al = g_a[ms][i][h] + a_d;
        al = al > 0.f ? al : 0.2f * al;
        float ea = __expf(al);
        den = ea;
        float4 v = *(const float4*)&g_Y[ms][i][c4 * 4];
        num.x = ea * v.x; num.y = ea * v.y; num.z = ea * v.z; num.w = ea * v.w;
    }

    int beg = g_off[dir][i], end = g_off[dir][i + 1];
    for (int j = beg + half; j < end; j += 2) {
        int s = g_srcs[dir][j];
        float al = g_a[ms][s][h] + a_d;
        al = al > 0.f ? al : 0.2f * al;
        float ea = __expf(al);
        den += ea;
        float4 v = *(const float4*)&g_Y[ms][s][c4 * 4];
        num.x = fmaf(ea, v.x, num.x);
        num.y = fmaf(ea, v.y, num.y);
        num.z = fmaf(ea, v.z, num.z);
        num.w = fmaf(ea, v.w, num.w);
    }

    num.x += __shfl_xor_sync(0xffffffffu, num.x, 16);
    num.y += __shfl_xor_sync(0xffffffffu, num.y, 16);
    num.z += __shfl_xor_sync(0xffffffffu, num.z, 16);
    num.w += __shfl_xor_sync(0xffffffffu, num.w, 16);
    den   += __shfl_xor_sync(0xffffffffu, den,   16);

    if (half == 0) {
        float w = 1.f / (den + 1e-16f);
        float4 b = ((const float4*)bias)[c4];
        float4 o = make_float4(fmaf(num.x, w, b.x), fmaf(num.y, w, b.y),
                               fmaf(num.z, w, b.z), fmaf(num.w, w, b.w));
        float* dp = out + ((dir == 0) ? (size_t)NN * 64 : (size_t)0)
                        + (size_t)i * 64 + c4 * 4;
        *(float4*)dp = o;
    }
}

extern "C" void kernel_launch(void* const* d_in, const int* in_sizes, int n_in,
                              void* d_out, int out_size) {
    const float* hx      = (const float*)d_in[0];
    const float* txp     = (const float*)d_in[1];
    const void*  ei      = d_in[2];               // int32 or int64, auto-detected
    const float* Wsrc    = (const float*)d_in[3];
    const float* Wdst    = (const float*)d_in[4];
    const float* att_src = (const float*)d_in[5];
    const float* att_dst = (const float*)d_in[6];
    const float* bias    = (const float*)d_in[7];
    float* out = (float*)d_out;

    detect_kernel<<<1, 32>>>((const int*)ei);
    prep_wv_kernel<<<4, 256>>>(Wsrc, Wdst, att_src, att_dst);
    zero_kernel<<<(2 * NN + 255) / 256, 256>>>();
    gemm_kernel<<<dim3((NN + 127) / 128, 2), 256>>>(hx, txp, Wsrc, att_src);
    hist_kernel<<<(EE + 255) / 256, 256>>>(ei);
    scan1_kernel<<<dim3(NB, 2), 256>>>();
    scan2_kernel<<<2, 256>>>();
    scan3_kernel<<<dim3(NB, 2), 256>>>();
    scatter_kernel<<<(EE + 255) / 256, 256>>>(ei);
    aggr_kernel<<<(2 * NN * 32 + 255) / 256, 256>>>(out, bias);
}